// round 5
// baseline (speedup 1.0000x reference)
#include <cuda_runtime.h>
#include <math.h>

#define N_SAMP 1024
#define XD 768
#define LOWER 300
#define NJ 8          // number of j-splits in pair kernel
#define TI 32         // i tile (rows of hy)
#define TJ 128        // j tile (rows of hxb)
#define KC 60         // K chunk (300 = 5 * 60)

typedef unsigned long long ull;

// scratch (static device arrays: no allocation allowed in kernel_launch)
__device__ float  g_hxbT[LOWER * N_SAMP];  // [k][j]  = (x @ Wx + b1)^T
__device__ float  g_hyT [LOWER * N_SAMP];  // [k][i]  = (y @ Wy)^T
__device__ float2 g_part[N_SAMP * NJ];     // per-row partial (max, sumexp)
__device__ float  g_T0  [N_SAMP];          // softplus(logit[i,i])

// ---- f32x2 packed helpers (sm_103a FFMA2/FADD2 via PTX) ----
__device__ __forceinline__ ull splat2(float v) {
    ull r; asm("mov.b64 %0, {%1, %1};" : "=l"(r) : "f"(v)); return r;
}
__device__ __forceinline__ ull add2(ull a, ull b) {
    ull d; asm("add.rn.f32x2 %0, %1, %2;" : "=l"(d) : "l"(a), "l"(b)); return d;
}
__device__ __forceinline__ ull fma2(ull a, ull b, ull c) {
    ull d; asm("fma.rn.f32x2 %0, %1, %2, %3;" : "=l"(d) : "l"(a), "l"(b), "l"(c)); return d;
}
__device__ __forceinline__ void unpk2(ull v, float& lo, float& hi) {
    asm("mov.b64 {%0, %1}, %2;" : "=f"(lo), "=f"(hi) : "l"(v));
}
__device__ __forceinline__ ull relu2(ull t) {
    float lo, hi;
    asm("mov.b64 {%0, %1}, %2;" : "=f"(lo), "=f"(hi) : "l"(t));
    lo = fmaxf(lo, 0.f); hi = fmaxf(hi, 0.f);
    ull r; asm("mov.b64 %0, {%1, %2};" : "=l"(r) : "f"(lo), "f"(hi)); return r;
}

// ---------------------------------------------------------------------------
// GEMM: outT[c][n] = sum_d A[n][d] * W[d][c] (+ bias[c])
// z=0: A=x, W=W1[0:768],   bias=b1, out=g_hxbT
// z=1: A=y, W=W1[768:1536], no bias, out=g_hyT
// BM=64(n), BN=64(c), BK=16, 128 threads, per-thread 8(n, as 4 f32x2 pairs) x 4(c)
// ---------------------------------------------------------------------------
#define ASTRIDE 68
#define BSTRIDE 68

__global__ __launch_bounds__(128)
void gemm_kernel(const float* __restrict__ x,
                 const float* __restrict__ y,
                 const float* __restrict__ W1,
                 const float* __restrict__ b1) {
    __shared__ float As[16 * ASTRIDE];   // [k][n]
    __shared__ float Bs[16 * BSTRIDE];   // [k][c]

    int tid = threadIdx.x;
    int tx = tid & 7;          // n-group: n-sub = tx*8
    int ty = tid >> 3;         // c-group: c-sub = ty*4 (0..15)

    int n0 = blockIdx.x * 64;
    int c0 = blockIdx.y * 64;

    const float* A;
    const float* W;
    float* outT;
    bool hasBias;
    if (blockIdx.z == 0) { A = x; W = W1;               hasBias = true;  outT = g_hxbT; }
    else                 { A = y; W = W1 + XD * LOWER;  hasBias = false; outT = g_hyT;  }

    ull acc2[4][4] = {};   // [n-pair p][c]; zero bits == (0.f, 0.f)

    // A stage mapping: 64 rows x 4 float4-cols -> 2 float4 per thread
    int a_row = tid >> 1;            // 0..63
    int a_qb  = (tid & 1) * 2;       // float4-col base: 0 or 2
    // B stage mapping: 16 k-rows x 16 float4-cols -> 2 float4 per thread
    int b_k  = tid & 15;             // 0..15
    int b_cb = (tid >> 4) * 8;       // 0,8,...,56; two float4 at +0, +4

    for (int k0 = 0; k0 < XD; k0 += 16) {
        #pragma unroll
        for (int q = 0; q < 2; q++) {
            int kq = (a_qb + q) * 4;
            float4 av = *(const float4*)&A[(n0 + a_row) * XD + k0 + kq];
            As[(kq + 0) * ASTRIDE + a_row] = av.x;
            As[(kq + 1) * ASTRIDE + a_row] = av.y;
            As[(kq + 2) * ASTRIDE + a_row] = av.z;
            As[(kq + 3) * ASTRIDE + a_row] = av.w;
        }
        #pragma unroll
        for (int q = 0; q < 2; q++) {
            int c = b_cb + q * 4;
            float4 bv = make_float4(0.f, 0.f, 0.f, 0.f);
            if (c0 + c < LOWER)
                bv = *(const float4*)&W[(k0 + b_k) * LOWER + c0 + c];
            *(float4*)&Bs[b_k * BSTRIDE + c] = bv;
        }
        __syncthreads();

        #pragma unroll
        for (int k = 0; k < 16; k++) {
            // 8 n-values as 4 packed pairs (two 16B loads)
            ulonglong2 al = *(const ulonglong2*)&As[k * ASTRIDE + tx * 8];
            ulonglong2 ah = *(const ulonglong2*)&As[k * ASTRIDE + tx * 8 + 4];
            ull a2[4] = {al.x, al.y, ah.x, ah.y};
            float4 bv = *(const float4*)&Bs[k * BSTRIDE + ty * 4];
            float bc[4] = {bv.x, bv.y, bv.z, bv.w};
            #pragma unroll
            for (int c = 0; c < 4; c++) {
                ull bs = splat2(bc[c]);
                #pragma unroll
                for (int p = 0; p < 4; p++)
                    acc2[p][c] = fma2(a2[p], bs, acc2[p][c]);
            }
        }
        __syncthreads();
    }

    #pragma unroll
    for (int c = 0; c < 4; c++) {
        int gc = c0 + ty * 4 + c;
        if (gc < LOWER) {
            float bias = hasBias ? b1[gc] : 0.f;
            #pragma unroll
            for (int p = 0; p < 4; p++) {
                float lo, hi;
                unpk2(acc2[p][c], lo, hi);
                int gn = n0 + tx * 8 + 2 * p;
                outT[gc * N_SAMP + gn]     = lo + bias;
                outT[gc * N_SAMP + gn + 1] = hi + bias;
            }
        }
    }
}

// ---------------------------------------------------------------------------
// Pair kernel: block = (32 i-rows) x (128 j-cols), full K=300.
// logit[i,j] = sum_k relu(hy[i,k] + hxb[j,k]) * w2[k] + b2
// i-dimension packed as f32x2 pairs: acc2[p][c] holds rows warp*4+2p, +2p+1.
// ---------------------------------------------------------------------------
__global__ __launch_bounds__(256)
void pair_kernel(const float* __restrict__ W2,
                 const float* __restrict__ b2p) {
    __shared__ float sHy[KC * TI];
    __shared__ float sHx[KC * TJ];
    __shared__ float sW[KC];

    int tid  = threadIdx.x;       // 0..255
    int warp = tid >> 5;          // 0..7  -> i sub-tile (4 rows)
    int lane = tid & 31;          // 0..31 -> j sub-tile (4 cols)
    int i0 = blockIdx.x * TI;
    int j0 = blockIdx.y * TJ;

    ull acc2[2][4] = {};          // [i-pair p][c]

    for (int k0 = 0; k0 < LOWER; k0 += KC) {
        #pragma unroll
        for (int idx = tid; idx < KC * TI; idx += 256) {
            int kk = idx >> 5, ii = idx & 31;
            sHy[idx] = g_hyT[(k0 + kk) * N_SAMP + i0 + ii];
        }
        #pragma unroll
        for (int idx = tid; idx < KC * TJ; idx += 256) {
            int kk = idx >> 7, jj = idx & 127;
            sHx[idx] = g_hxbT[(k0 + kk) * N_SAMP + j0 + jj];
        }
        if (tid < KC) sW[tid] = W2[k0 + tid];
        __syncthreads();

        #pragma unroll 10
        for (int k = 0; k < KC; k++) {
            // 4 i-rows as 2 packed pairs (one 16B load)
            ulonglong2 hv = *(const ulonglong2*)&sHy[k * TI + warp * 4];
            ull hy2[2] = {hv.x, hv.y};
            float4 xv = *(const float4*)&sHx[k * TJ + lane * 4];
            float hx[4] = {xv.x, xv.y, xv.z, xv.w};
            ull ws = splat2(sW[k]);
            #pragma unroll
            for (int c = 0; c < 4; c++) {
                ull hs = splat2(hx[c]);
                #pragma unroll
                for (int p = 0; p < 2; p++) {
                    ull t = relu2(add2(hy2[p], hs));
                    acc2[p][c] = fma2(t, ws, acc2[p][c]);
                }
            }
        }
        __syncthreads();
    }

    // unpack to scalar [r][c] layout (r = 2p + half)
    float accs[4][4];
    #pragma unroll
    for (int p = 0; p < 2; p++)
        #pragma unroll
        for (int c = 0; c < 4; c++)
            unpk2(acc2[p][c], accs[2 * p][c], accs[2 * p + 1][c]);

    float b2 = *b2p;
    #pragma unroll
    for (int r = 0; r < 4; r++) {
        int gi = i0 + warp * 4 + r;
        float sp[4];
        float m = -1e30f;
        #pragma unroll
        for (int c = 0; c < 4; c++) {
            float l = accs[r][c] + b2;
            float s = fmaxf(l, 0.f) + log1pf(expf(-fabsf(l)));
            sp[c] = s;
            int gj = j0 + lane * 4 + c;
            if (gj == gi) g_T0[gi] = s;
            m = fmaxf(m, s);
        }
        #pragma unroll
        for (int o = 16; o; o >>= 1)
            m = fmaxf(m, __shfl_xor_sync(0xffffffffu, m, o));
        float ssum = 0.f;
        #pragma unroll
        for (int c = 0; c < 4; c++) ssum += expf(sp[c] - m);
        #pragma unroll
        for (int o = 16; o; o >>= 1)
            ssum += __shfl_xor_sync(0xffffffffu, ssum, o);
        if (lane == 0) g_part[gi * NJ + blockIdx.y] = make_float2(m, ssum);
    }
}

// ---------------------------------------------------------------------------
// Finalize: combine NJ partials per row -> logsumexp; reduce T0 and lse means.
// ---------------------------------------------------------------------------
__global__ __launch_bounds__(1024)
void finalize_kernel(float* __restrict__ out) {
    int i = threadIdx.x;  // 1024 threads
    float M = -1e30f;
    float2 p[NJ];
    #pragma unroll
    for (int j = 0; j < NJ; j++) {
        p[j] = g_part[i * NJ + j];
        M = fmaxf(M, p[j].x);
    }
    float S = 0.f;
    #pragma unroll
    for (int j = 0; j < NJ; j++) S += p[j].y * expf(p[j].x - M);
    float lse = M + logf(S);
    float t0  = g_T0[i];

    __shared__ float sA[1024];
    __shared__ float sB[1024];
    sA[i] = t0;
    sB[i] = lse;
    __syncthreads();
    for (int s = 512; s; s >>= 1) {
        if (i < s) { sA[i] += sA[i + s]; sB[i] += sB[i + s]; }
        __syncthreads();
    }
    if (i == 0)
        out[0] = sA[0] / (float)N_SAMP - sB[0] / (float)N_SAMP - logf((float)N_SAMP);
}

extern "C" void kernel_launch(void* const* d_in, const int* in_sizes, int n_in,
                              void* d_out, int out_size) {
    const float* x  = (const float*)d_in[0];
    const float* y  = (const float*)d_in[1];
    const float* W1 = (const float*)d_in[2];
    const float* b1 = (const float*)d_in[3];
    const float* W2 = (const float*)d_in[4];
    const float* b2 = (const float*)d_in[5];
    float* out = (float*)d_out;

    gemm_kernel<<<dim3(16, 5, 2), 128>>>(x, y, W1, b1);
    pair_kernel<<<dim3(32, 8), 256>>>(W2, b2);
    finalize_kernel<<<1, 1024>>>(out);
}

// round 10
// speedup vs baseline: 1.1767x; 1.1767x over previous
#include <cuda_runtime.h>
#include <math.h>

#define N_SAMP 1024
#define XD 768
#define LOWER 300
#define NJ 8          // number of j-splits in pair kernel
#define TI 32         // i tile (rows of hy)
#define TJ 128        // j tile (rows of hxb)
#define KC 60         // K chunk (300 = 5 * 60)
#define KHALF 384     // split-K half of XD

typedef unsigned long long ull;

// scratch (static device arrays: no allocation allowed in kernel_launch)
// split-K partial results; pair kernel sums the two halves while staging.
__device__ float  g_hxbT0[LOWER * N_SAMP];  // [k][j] partial (x @ Wx)[:, k<384] + b1
__device__ float  g_hxbT1[LOWER * N_SAMP];  // [k][j] partial (x @ Wx)[:, k>=384]
__device__ float  g_hyT0 [LOWER * N_SAMP];  // [k][i] partial (y @ Wy)
__device__ float  g_hyT1 [LOWER * N_SAMP];
__device__ float2 g_part[N_SAMP * NJ];      // per-row partial (max, sumexp)
__device__ float  g_T0  [N_SAMP];           // softplus(logit[i,i])

// ---- f32x2 packed helpers (sm_103a FFMA2/FADD2 via PTX) ----
__device__ __forceinline__ ull splat2(float v) {
    ull r; asm("mov.b64 %0, {%1, %1};" : "=l"(r) : "f"(v)); return r;
}
__device__ __forceinline__ ull add2(ull a, ull b) {
    ull d; asm("add.rn.f32x2 %0, %1, %2;" : "=l"(d) : "l"(a), "l"(b)); return d;
}
__device__ __forceinline__ ull fma2(ull a, ull b, ull c) {
    ull d; asm("fma.rn.f32x2 %0, %1, %2, %3;" : "=l"(d) : "l"(a), "l"(b), "l"(c)); return d;
}
__device__ __forceinline__ void unpk2(ull v, float& lo, float& hi) {
    asm("mov.b64 {%0, %1}, %2;" : "=f"(lo), "=f"(hi) : "l"(v));
}
__device__ __forceinline__ ull relu2(ull t) {
    float lo, hi;
    asm("mov.b64 {%0, %1}, %2;" : "=f"(lo), "=f"(hi) : "l"(t));
    lo = fmaxf(lo, 0.f); hi = fmaxf(hi, 0.f);
    ull r; asm("mov.b64 %0, {%1, %2};" : "=l"(r) : "f"(lo), "f"(hi)); return r;
}

// ---------------------------------------------------------------------------
// GEMM (split-K): outT[c][n] = sum_{d in half} A[n][d] * W[d][c] (+ bias[c])
// blockIdx.z: bit0 = source (0: x->hxb, 1: y->hy), bit1 = K half.
// BM=64(n), BN=64(c), BK=16, 256 threads, per-thread 4n(2 f32x2 pairs) x 4c.
// grid (16, 5, 4) = 320 blocks -> 2 CTAs/SM -> 16 warps/SM.
// ---------------------------------------------------------------------------
#define ASTR 68
#define BSTR 68

__global__ __launch_bounds__(256)
void gemm_kernel(const float* __restrict__ x,
                 const float* __restrict__ y,
                 const float* __restrict__ W1,
                 const float* __restrict__ b1) {
    __shared__ float As[16 * ASTR];   // [k][n]
    __shared__ float Bs[16 * BSTR];   // [k][c]

    int tid = threadIdx.x;
    int tx = tid & 15;         // n-group: n = tx*4
    int ty = tid >> 4;         // c-group: c = ty*4

    int n0 = blockIdx.x * 64;
    int c0 = blockIdx.y * 64;
    int src  = blockIdx.z & 1;
    int half = blockIdx.z >> 1;

    const float* A = src ? y : x;
    const float* W = W1 + src * XD * LOWER;
    float* outT = src ? (half ? g_hyT1 : g_hyT0)
                      : (half ? g_hxbT1 : g_hxbT0);
    bool hasBias = (src == 0) && (half == 0);
    int kbase = half * KHALF;

    ull acc2[2][4] = {};   // [n-pair p][c]

    // A stage: 64 rows x 16 k -> 256 threads x 1 float4
    int a_row = tid & 63;             // 0..63
    int a_kq  = (tid >> 6) * 4;       // 0,4,8,12
    // B stage: 16 k x 64 c -> 256 threads x 1 float4
    int b_k = tid & 15;               // 0..15
    int b_c = (tid >> 4) * 4;         // 0..60

    for (int k0 = 0; k0 < KHALF; k0 += 16) {
        float4 av = *(const float4*)&A[(n0 + a_row) * XD + kbase + k0 + a_kq];
        As[(a_kq + 0) * ASTR + a_row] = av.x;
        As[(a_kq + 1) * ASTR + a_row] = av.y;
        As[(a_kq + 2) * ASTR + a_row] = av.z;
        As[(a_kq + 3) * ASTR + a_row] = av.w;

        float4 bv = make_float4(0.f, 0.f, 0.f, 0.f);
        if (c0 + b_c < LOWER)
            bv = *(const float4*)&W[(kbase + k0 + b_k) * LOWER + c0 + b_c];
        *(float4*)&Bs[b_k * BSTR + b_c] = bv;

        __syncthreads();
        #pragma unroll
        for (int k = 0; k < 16; k++) {
            // 4 n-values as 2 packed pairs: one 16B lane-contiguous load
            ulonglong2 al = *(const ulonglong2*)&As[k * ASTR + tx * 4];
            ull a2[2] = {al.x, al.y};
            float4 bw = *(const float4*)&Bs[k * BSTR + ty * 4];
            float bc[4] = {bw.x, bw.y, bw.z, bw.w};
            #pragma unroll
            for (int c = 0; c < 4; c++) {
                ull bs = splat2(bc[c]);
                #pragma unroll
                for (int p = 0; p < 2; p++)
                    acc2[p][c] = fma2(a2[p], bs, acc2[p][c]);
            }
        }
        __syncthreads();
    }

    #pragma unroll
    for (int c = 0; c < 4; c++) {
        int gc = c0 + ty * 4 + c;
        if (gc < LOWER) {
            float bias = hasBias ? b1[gc] : 0.f;
            #pragma unroll
            for (int p = 0; p < 2; p++) {
                float lo, hi;
                unpk2(acc2[p][c], lo, hi);
                int gn = n0 + tx * 4 + 2 * p;
                outT[gc * N_SAMP + gn]     = lo + bias;
                outT[gc * N_SAMP + gn + 1] = hi + bias;
            }
        }
    }
}

// ---------------------------------------------------------------------------
// Pair kernel: block = (32 i-rows) x (128 j-cols), full K=300.
// logit[i,j] = sum_k relu(hy[i,k] + hxb[j,k]) * w2[k] + b2
// i-dimension packed as f32x2 pairs. Split-K halves summed during staging.
// ---------------------------------------------------------------------------
__global__ __launch_bounds__(256)
void pair_kernel(const float* __restrict__ W2,
                 const float* __restrict__ b2p) {
    __shared__ float sHy[KC * TI];
    __shared__ float sHx[KC * TJ];
    __shared__ float sW[KC];

    int tid  = threadIdx.x;       // 0..255
    int warp = tid >> 5;          // 0..7  -> i sub-tile (4 rows)
    int lane = tid & 31;          // 0..31 -> j sub-tile (4 cols)
    int i0 = blockIdx.x * TI;
    int j0 = blockIdx.y * TJ;

    ull acc2[2][4] = {};          // [i-pair p][c]

    for (int k0 = 0; k0 < LOWER; k0 += KC) {
        #pragma unroll
        for (int idx = tid; idx < KC * TI; idx += 256) {
            int kk = idx >> 5, ii = idx & 31;
            int off = (k0 + kk) * N_SAMP + i0 + ii;
            sHy[idx] = g_hyT0[off] + g_hyT1[off];
        }
        #pragma unroll
        for (int idx = tid; idx < KC * TJ; idx += 256) {
            int kk = idx >> 7, jj = idx & 127;
            int off = (k0 + kk) * N_SAMP + j0 + jj;
            sHx[idx] = g_hxbT0[off] + g_hxbT1[off];
        }
        if (tid < KC) sW[tid] = W2[k0 + tid];
        __syncthreads();

        #pragma unroll 10
        for (int k = 0; k < KC; k++) {
            // 4 i-rows as 2 packed pairs (one 16B load, warp-broadcast)
            ulonglong2 hv = *(const ulonglong2*)&sHy[k * TI + warp * 4];
            ull hy2[2] = {hv.x, hv.y};
            float4 xv = *(const float4*)&sHx[k * TJ + lane * 4];
            float hx[4] = {xv.x, xv.y, xv.z, xv.w};
            ull ws = splat2(sW[k]);
            #pragma unroll
            for (int c = 0; c < 4; c++) {
                ull hs = splat2(hx[c]);
                #pragma unroll
                for (int p = 0; p < 2; p++) {
                    ull t = relu2(add2(hy2[p], hs));
                    acc2[p][c] = fma2(t, ws, acc2[p][c]);
                }
            }
        }
        __syncthreads();
    }

    // unpack to scalar [r][c] layout (r = 2p + half)
    float accs[4][4];
    #pragma unroll
    for (int p = 0; p < 2; p++)
        #pragma unroll
        for (int c = 0; c < 4; c++)
            unpk2(acc2[p][c], accs[2 * p][c], accs[2 * p + 1][c]);

    float b2 = *b2p;
    #pragma unroll
    for (int r = 0; r < 4; r++) {
        int gi = i0 + warp * 4 + r;
        float sp[4];
        float m = -1e30f;
        #pragma unroll
        for (int c = 0; c < 4; c++) {
            float l = accs[r][c] + b2;
            float s = fmaxf(l, 0.f) + log1pf(expf(-fabsf(l)));
            sp[c] = s;
            int gj = j0 + lane * 4 + c;
            if (gj == gi) g_T0[gi] = s;
            m = fmaxf(m, s);
        }
        #pragma unroll
        for (int o = 16; o; o >>= 1)
            m = fmaxf(m, __shfl_xor_sync(0xffffffffu, m, o));
        float ssum = 0.f;
        #pragma unroll
        for (int c = 0; c < 4; c++) ssum += expf(sp[c] - m);
        #pragma unroll
        for (int o = 16; o; o >>= 1)
            ssum += __shfl_xor_sync(0xffffffffu, ssum, o);
        if (lane == 0) g_part[gi * NJ + blockIdx.y] = make_float2(m, ssum);
    }
}

// ---------------------------------------------------------------------------
// Finalize: combine NJ partials per row -> logsumexp; reduce T0 and lse means.
// ---------------------------------------------------------------------------
__global__ __launch_bounds__(1024)
void finalize_kernel(float* __restrict__ out) {
    int i = threadIdx.x;  // 1024 threads
    float M = -1e30f;
    float2 p[NJ];
    #pragma unroll
    for (int j = 0; j < NJ; j++) {
        p[j] = g_part[i * NJ + j];
        M = fmaxf(M, p[j].x);
    }
    float S = 0.f;
    #pragma unroll
    for (int j = 0; j < NJ; j++) S += p[j].y * expf(p[j].x - M);
    float lse = M + logf(S);
    float t0  = g_T0[i];

    __shared__ float sA[1024];
    __shared__ float sB[1024];
    sA[i] = t0;
    sB[i] = lse;
    __syncthreads();
    for (int s = 512; s; s >>= 1) {
        if (i < s) { sA[i] += sA[i + s]; sB[i] += sB[i + s]; }
        __syncthreads();
    }
    if (i == 0)
        out[0] = sA[0] / (float)N_SAMP - sB[0] / (float)N_SAMP - logf((float)N_SAMP);
}

extern "C" void kernel_launch(void* const* d_in, const int* in_sizes, int n_in,
                              void* d_out, int out_size) {
    const float* x  = (const float*)d_in[0];
    const float* y  = (const float*)d_in[1];
    const float* W1 = (const float*)d_in[2];
    const float* b1 = (const float*)d_in[3];
    const float* W2 = (const float*)d_in[4];
    const float* b2 = (const float*)d_in[5];
    float* out = (float*)d_out;

    gemm_kernel<<<dim3(16, 5, 4), 256>>>(x, y, W1, b1);
    pair_kernel<<<dim3(32, 8), 256>>>(W2, b2);
    finalize_kernel<<<1, 1024>>>(out);
}

// round 16
// speedup vs baseline: 1.3662x; 1.1610x over previous
#include <cuda_runtime.h>
#include <math.h>

#define N_SAMP 1024
#define XD 768
#define LOWER 300
#define NJ 8          // number of j-splits in pair kernel
#define TI 32         // i tile (rows of hy)
#define TJ 128        // j tile (rows of hxb)
#define KC 60         // K chunk (300 = 5 * 60)
#define KQ 192        // split-K quarter of XD
#define SLICE (LOWER * N_SAMP)

typedef unsigned long long ull;

// scratch (static device arrays: no allocation allowed in kernel_launch)
__device__ float  g_hxbP[4 * SLICE];   // 4 split-K partials of (x @ Wx) (+b1 in q0)
__device__ float  g_hyP [4 * SLICE];   // 4 split-K partials of (y @ Wy)
__device__ float  g_hxbT[SLICE];       // merged [k][j]
__device__ float  g_hyT [SLICE];       // merged [k][i]
__device__ float2 g_part[N_SAMP * NJ]; // per-row partial (max, sumexp)
__device__ float  g_T0  [N_SAMP];      // softplus(logit[i,i])

// ---- f32x2 packed helpers (sm_103a FFMA2/FADD2 via PTX) ----
__device__ __forceinline__ ull splat2(float v) {
    ull r; asm("mov.b64 %0, {%1, %1};" : "=l"(r) : "f"(v)); return r;
}
__device__ __forceinline__ ull add2(ull a, ull b) {
    ull d; asm("add.rn.f32x2 %0, %1, %2;" : "=l"(d) : "l"(a), "l"(b)); return d;
}
__device__ __forceinline__ ull fma2(ull a, ull b, ull c) {
    ull d; asm("fma.rn.f32x2 %0, %1, %2, %3;" : "=l"(d) : "l"(a), "l"(b), "l"(c)); return d;
}
__device__ __forceinline__ void unpk2(ull v, float& lo, float& hi) {
    asm("mov.b64 {%0, %1}, %2;" : "=f"(lo), "=f"(hi) : "l"(v));
}
__device__ __forceinline__ ull relu2(ull t) {
    float lo, hi;
    asm("mov.b64 {%0, %1}, %2;" : "=f"(lo), "=f"(hi) : "l"(t));
    lo = fmaxf(lo, 0.f); hi = fmaxf(hi, 0.f);
    ull r; asm("mov.b64 %0, {%1, %2};" : "=l"(r) : "f"(lo), "f"(hi)); return r;
}

// ---------------------------------------------------------------------------
// GEMM (split-K x4): partial[c][n] = sum_{d in quarter} A[n][d] * W[d][c]
// blockIdx.z: bit0 = source (0: x->hxb, 1: y->hy), bits[1:3] = K quarter.
// BM=64(n), BN=64(c), BK=16, 256 threads, per-thread 4n(2 f32x2 pairs) x 4c.
// grid (16, 5, 8) = 640 blocks -> 4 CTAs/SM -> 32 warps/SM.
// ---------------------------------------------------------------------------
#define ASTR 68
#define BSTR 68

__global__ __launch_bounds__(256)
void gemm_kernel(const float* __restrict__ x,
                 const float* __restrict__ y,
                 const float* __restrict__ W1,
                 const float* __restrict__ b1) {
    __shared__ float As[16 * ASTR];   // [k][n]
    __shared__ float Bs[16 * BSTR];   // [k][c]

    int tid = threadIdx.x;
    int tx = tid & 15;         // n-group: n = tx*4
    int ty = tid >> 4;         // c-group: c = ty*4

    int n0 = blockIdx.x * 64;
    int c0 = blockIdx.y * 64;
    int src  = blockIdx.z & 1;
    int q    = blockIdx.z >> 1;   // 0..3

    const float* A = src ? y : x;
    const float* W = W1 + src * XD * LOWER;
    float* outT = (src ? g_hyP : g_hxbP) + q * SLICE;
    bool hasBias = (src == 0) && (q == 0);
    int kbase = q * KQ;

    ull acc2[2][4] = {};   // [n-pair p][c]

    // A stage: 64 rows x 16 k -> 256 threads x 1 float4
    int a_row = tid & 63;             // 0..63
    int a_kq  = (tid >> 6) * 4;       // 0,4,8,12
    // B stage: 16 k x 64 c -> 256 threads x 1 float4
    int b_k = tid & 15;               // 0..15
    int b_c = (tid >> 4) * 4;         // 0..60

    for (int k0 = 0; k0 < KQ; k0 += 16) {
        float4 av = *(const float4*)&A[(n0 + a_row) * XD + kbase + k0 + a_kq];
        As[(a_kq + 0) * ASTR + a_row] = av.x;
        As[(a_kq + 1) * ASTR + a_row] = av.y;
        As[(a_kq + 2) * ASTR + a_row] = av.z;
        As[(a_kq + 3) * ASTR + a_row] = av.w;

        float4 bv = make_float4(0.f, 0.f, 0.f, 0.f);
        if (c0 + b_c < LOWER)
            bv = *(const float4*)&W[(kbase + k0 + b_k) * LOWER + c0 + b_c];
        *(float4*)&Bs[b_k * BSTR + b_c] = bv;

        __syncthreads();
        #pragma unroll
        for (int k = 0; k < 16; k++) {
            // 4 n-values as 2 packed pairs: one 16B lane-contiguous load
            ulonglong2 al = *(const ulonglong2*)&As[k * ASTR + tx * 4];
            ull a2[2] = {al.x, al.y};
            float4 bw = *(const float4*)&Bs[k * BSTR + ty * 4];
            float bc[4] = {bw.x, bw.y, bw.z, bw.w};
            #pragma unroll
            for (int c = 0; c < 4; c++) {
                ull bs = splat2(bc[c]);
                #pragma unroll
                for (int p = 0; p < 2; p++)
                    acc2[p][c] = fma2(a2[p], bs, acc2[p][c]);
            }
        }
        __syncthreads();
    }

    #pragma unroll
    for (int c = 0; c < 4; c++) {
        int gc = c0 + ty * 4 + c;
        if (gc < LOWER) {
            float bias = hasBias ? b1[gc] : 0.f;
            #pragma unroll
            for (int p = 0; p < 2; p++) {
                float lo, hi;
                unpk2(acc2[p][c], lo, hi);
                int gn = n0 + tx * 4 + 2 * p;
                outT[gc * N_SAMP + gn]     = lo + bias;
                outT[gc * N_SAMP + gn + 1] = hi + bias;
            }
        }
    }
}

// ---------------------------------------------------------------------------
// Merge: g_hxbT = sum of 4 hxb partials; g_hyT = sum of 4 hy partials.
// float4-vectorized, fixed summation order (deterministic).
// ---------------------------------------------------------------------------
__global__ __launch_bounds__(256)
void merge_kernel() {
    int i4 = blockIdx.x * 256 + threadIdx.x;   // float4 index
    const int NV = SLICE / 4;                  // 76800
    if (i4 < NV) {
        const float4* p0 = (const float4*)g_hxbP;
        float4 a = p0[i4], b = p0[NV + i4], c = p0[2 * NV + i4], d = p0[3 * NV + i4];
        float4 s;
        s.x = ((a.x + b.x) + c.x) + d.x;
        s.y = ((a.y + b.y) + c.y) + d.y;
        s.z = ((a.z + b.z) + c.z) + d.z;
        s.w = ((a.w + b.w) + c.w) + d.w;
        ((float4*)g_hxbT)[i4] = s;

        const float4* q0 = (const float4*)g_hyP;
        float4 e = q0[i4], f = q0[NV + i4], g = q0[2 * NV + i4], h = q0[3 * NV + i4];
        float4 t;
        t.x = ((e.x + f.x) + g.x) + h.x;
        t.y = ((e.y + f.y) + g.y) + h.y;
        t.z = ((e.z + f.z) + g.z) + h.z;
        t.w = ((e.w + f.w) + g.w) + h.w;
        ((float4*)g_hyT)[i4] = t;
    }
}

// ---------------------------------------------------------------------------
// Pair kernel: block = (32 i-rows) x (128 j-cols), full K=300.
// logit[i,j] = sum_k relu(hy[i,k] + hxb[j,k]) * w2[k] + b2
// i-dimension packed as f32x2 pairs.
// ---------------------------------------------------------------------------
__global__ __launch_bounds__(256)
void pair_kernel(const float* __restrict__ W2,
                 const float* __restrict__ b2p) {
    __shared__ float sHy[KC * TI];
    __shared__ float sHx[KC * TJ];
    __shared__ float sW[KC];

    int tid  = threadIdx.x;       // 0..255
    int warp = tid >> 5;          // 0..7  -> i sub-tile (4 rows)
    int lane = tid & 31;          // 0..31 -> j sub-tile (4 cols)
    int i0 = blockIdx.x * TI;
    int j0 = blockIdx.y * TJ;

    ull acc2[2][4] = {};          // [i-pair p][c]

    for (int k0 = 0; k0 < LOWER; k0 += KC) {
        #pragma unroll
        for (int idx = tid; idx < KC * TI; idx += 256) {
            int kk = idx >> 5, ii = idx & 31;
            sHy[idx] = g_hyT[(k0 + kk) * N_SAMP + i0 + ii];
        }
        #pragma unroll
        for (int idx = tid; idx < KC * TJ; idx += 256) {
            int kk = idx >> 7, jj = idx & 127;
            sHx[idx] = g_hxbT[(k0 + kk) * N_SAMP + j0 + jj];
        }
        if (tid < KC) sW[tid] = W2[k0 + tid];
        __syncthreads();

        #pragma unroll 10
        for (int k = 0; k < KC; k++) {
            // 4 i-rows as 2 packed pairs (one 16B load, warp-broadcast)
            ulonglong2 hv = *(const ulonglong2*)&sHy[k * TI + warp * 4];
            ull hy2[2] = {hv.x, hv.y};
            float4 xv = *(const float4*)&sHx[k * TJ + lane * 4];
            float hx[4] = {xv.x, xv.y, xv.z, xv.w};
            ull ws = splat2(sW[k]);
            #pragma unroll
            for (int c = 0; c < 4; c++) {
                ull hs = splat2(hx[c]);
                #pragma unroll
                for (int p = 0; p < 2; p++) {
                    ull t = relu2(add2(hy2[p], hs));
                    acc2[p][c] = fma2(t, ws, acc2[p][c]);
                }
            }
        }
        __syncthreads();
    }

    // unpack to scalar [r][c] layout (r = 2p + half)
    float accs[4][4];
    #pragma unroll
    for (int p = 0; p < 2; p++)
        #pragma unroll
        for (int c = 0; c < 4; c++)
            unpk2(acc2[p][c], accs[2 * p][c], accs[2 * p + 1][c]);

    float b2 = *b2p;
    #pragma unroll
    for (int r = 0; r < 4; r++) {
        int gi = i0 + warp * 4 + r;
        float sp[4];
        float m = -1e30f;
        #pragma unroll
        for (int c = 0; c < 4; c++) {
            float l = accs[r][c] + b2;
            float s = fmaxf(l, 0.f) + log1pf(expf(-fabsf(l)));
            sp[c] = s;
            int gj = j0 + lane * 4 + c;
            if (gj == gi) g_T0[gi] = s;
            m = fmaxf(m, s);
        }
        #pragma unroll
        for (int o = 16; o; o >>= 1)
            m = fmaxf(m, __shfl_xor_sync(0xffffffffu, m, o));
        float ssum = 0.f;
        #pragma unroll
        for (int c = 0; c < 4; c++) ssum += expf(sp[c] - m);
        #pragma unroll
        for (int o = 16; o; o >>= 1)
            ssum += __shfl_xor_sync(0xffffffffu, ssum, o);
        if (lane == 0) g_part[gi * NJ + blockIdx.y] = make_float2(m, ssum);
    }
}

// ---------------------------------------------------------------------------
// Finalize: combine NJ partials per row -> logsumexp; reduce T0 and lse means.
// ---------------------------------------------------------------------------
__global__ __launch_bounds__(1024)
void finalize_kernel(float* __restrict__ out) {
    int i = threadIdx.x;  // 1024 threads
    float M = -1e30f;
    float2 p[NJ];
    #pragma unroll
    for (int j = 0; j < NJ; j++) {
        p[j] = g_part[i * NJ + j];
        M = fmaxf(M, p[j].x);
    }
    float S = 0.f;
    #pragma unroll
    for (int j = 0; j < NJ; j++) S += p[j].y * expf(p[j].x - M);
    float lse = M + logf(S);
    float t0  = g_T0[i];

    __shared__ float sA[1024];
    __shared__ float sB[1024];
    sA[i] = t0;
    sB[i] = lse;
    __syncthreads();
    for (int s = 512; s; s >>= 1) {
        if (i < s) { sA[i] += sA[i + s]; sB[i] += sB[i + s]; }
        __syncthreads();
    }
    if (i == 0)
        out[0] = sA[0] / (float)N_SAMP - sB[0] / (float)N_SAMP - logf((float)N_SAMP);
}

extern "C" void kernel_launch(void* const* d_in, const int* in_sizes, int n_in,
                              void* d_out, int out_size) {
    const float* x  = (const float*)d_in[0];
    const float* y  = (const float*)d_in[1];
    const float* W1 = (const float*)d_in[2];
    const float* b1 = (const float*)d_in[3];
    const float* W2 = (const float*)d_in[4];
    const float* b2 = (const float*)d_in[5];
    float* out = (float*)d_out;

    gemm_kernel<<<dim3(16, 5, 8), 256>>>(x, y, W1, b1);
    merge_kernel<<<300, 256>>>();
    pair_kernel<<<dim3(32, 8), 256>>>(W2, b2);
    finalize_kernel<<<1, 1024>>>(out);
}